// round 8
// baseline (speedup 1.0000x reference)
#include <cuda_runtime.h>
#include <math.h>

#define NB 2
#define NF 4096
#define NQ 16384
#define NPTS (NB*NQ)                  // 32768
#define BLOCK 128
#define SPLITS 4
#define TRIS_PER_SPLIT (NF/SPLITS)    // 1024
#define PAIRS_PER_SPLIT (TRIS_PER_SPLIT/2)  // 512
#define TILE_PAIRS 128                // 256 triangles per smem tile

typedef unsigned long long u64;

// Scratch (static __device__ arrays: allowed; no allocs anywhere)
__device__ float4 g_tc2[NB*(NF/2)*10];   // pair-interleaved eval consts
__device__ float4 g_nr2[NB*(NF/2)*2];    // pair-interleaved plane: {nx,ny,nz,-d} x2 lanes
__device__ int    g_order[NPTS];         // morton-sorted point order per batch
__device__ uint2  g_cand[NPTS*SPLITS];   // per (point,split): top-2 triangle indices

// ---- f32x2 packed helpers (sm_100a) ----
__device__ __forceinline__ u64 f2pack(float lo, float hi) {
    u64 r; asm("mov.b64 %0, {%1, %2};" : "=l"(r) : "f"(lo), "f"(hi)); return r;
}
__device__ __forceinline__ void f2unpack(u64 v, float& lo, float& hi) {
    asm("mov.b64 {%0, %1}, %2;" : "=f"(lo), "=f"(hi) : "l"(v));
}
__device__ __forceinline__ u64 f2add(u64 a, u64 b) {
    u64 r; asm("add.rn.f32x2 %0, %1, %2;" : "=l"(r) : "l"(a), "l"(b)); return r;
}
__device__ __forceinline__ u64 f2mul(u64 a, u64 b) {
    u64 r; asm("mul.rn.f32x2 %0, %1, %2;" : "=l"(r) : "l"(a), "l"(b)); return r;
}
__device__ __forceinline__ u64 f2fma(u64 a, u64 b, u64 c) {
    u64 r; asm("fma.rn.f32x2 %0, %1, %2, %3;" : "=l"(r) : "l"(a), "l"(b), "l"(c)); return r;
}

__device__ __forceinline__ float guard_inv(float x) {
    return (fabsf(x) > 1e-12f) ? (1.0f / x) : 1.0f;
}
__device__ __forceinline__ double dclamp01(double x) {
    return fmin(fmax(x, 0.0), 1.0);
}
__device__ __forceinline__ double dsafe_div(double num, double den) {
    double d = (fabs(den) > 1e-12) ? den : 1.0;
    return num / d;
}

// ---------------------------------------------------------------------------
// Kernel 0: per-triangle constants (pair-interleaved, pre-negated) + unit
// plane normal {nx,ny,nz,-n.a} for the distance lower bound.
// ---------------------------------------------------------------------------
__global__ void k_pre(const float* __restrict__ tris) {
    int i = blockIdx.x * blockDim.x + threadIdx.x;
    if (i >= NB * NF) return;
    const float* t = tris + (size_t)i * 9;
    float ax = t[0], ay = t[1], az = t[2];
    float bx = t[3], by = t[4], bz = t[5];
    float cx = t[6], cy = t[7], cz = t[8];
    float abx = bx - ax, aby = by - ay, abz = bz - az;
    float acx = cx - ax, acy = cy - ay, acz = cz - az;
    float aa = abx*abx + aby*aby + abz*abz;
    float bb = acx*acx + acy*acy + acz*acz;
    float gg = abx*acx + aby*acy + abz*acz;
    float cb2 = aa + bb - 2.0f*gg;
    float den = aa*bb - gg*gg;

    int pi = i >> 1, lane = i & 1;
    float* o = ((float*)g_tc2) + (size_t)pi * 40 + lane;
    o[ 0] = -ax;  o[ 2] = -ay;  o[ 4] = -az;
    o[ 6] = abx;  o[ 8] = aby;  o[10] = abz;
    o[12] = acx;  o[14] = acy;  o[16] = acz;
    o[18] = aa;   o[20] = bb;   o[22] = -gg;
    o[24] = -guard_inv(aa);  o[26] = -guard_inv(bb);
    o[28] = -guard_inv(cb2); o[30] = -guard_inv(den);
    o[32] = aa - gg; o[34] = cb2; o[36] = den; o[38] = 0.0f;

    // unit plane normal; degenerate -> zeros (never prunes)
    float nx = aby*acz - abz*acy;
    float ny = abz*acx - abx*acz;
    float nz = abx*acy - aby*acx;
    float nl = sqrtf(nx*nx + ny*ny + nz*nz);
    float inl = (nl > 1e-20f) ? (1.0f / nl) : 0.0f;
    nx *= inl; ny *= inl; nz *= inl;
    float* on = ((float*)g_nr2) + (size_t)pi * 8 + lane;
    on[0] = nx; on[2] = ny; on[4] = nz;
    on[6] = -(nx*ax + ny*ay + nz*az);
}

// ---------------------------------------------------------------------------
// Morton helpers + deterministic in-SMEM bitonic sort of points (per batch).
// (verbatim from R5 — verified correct there)
// ---------------------------------------------------------------------------
__device__ __forceinline__ unsigned expand3(unsigned v) {
    v &= 0x3FFu;
    v = (v | (v << 16)) & 0x030000FFu;
    v = (v | (v <<  8)) & 0x0300F00Fu;
    v = (v | (v <<  4)) & 0x030C30C3u;
    v = (v | (v <<  2)) & 0x09249249u;
    return v;
}
__device__ __forceinline__ unsigned q6(float x) {
    int v = (int)((x + 4.0f) * 8.0f);
    return (unsigned)max(0, min(63, v));
}

__global__ void k_sort(const float* __restrict__ pts) {
    extern __shared__ unsigned s[];
    int b = blockIdx.x;
    for (int i = threadIdx.x; i < NQ; i += blockDim.x) {
        const float* p = pts + (size_t)(b * NQ + i) * 3;
        unsigned m = expand3(q6(p[0])) | (expand3(q6(p[1])) << 1) | (expand3(q6(p[2])) << 2);
        s[i] = (m << 14) | (unsigned)i;
    }
    __syncthreads();
    for (unsigned k = 2; k <= (unsigned)NQ; k <<= 1) {
        for (unsigned j = k >> 1; j > 0; j >>= 1) {
            for (unsigned i = threadIdx.x; i < (unsigned)NQ; i += blockDim.x) {
                unsigned ix = i ^ j;
                if (ix > i) {
                    unsigned va = s[i], vb = s[ix];
                    bool up = ((i & k) == 0);
                    if ((va > vb) == up) { s[i] = vb; s[ix] = va; }
                }
            }
            __syncthreads();
        }
    }
    for (int i = threadIdx.x; i < NQ; i += blockDim.x)
        g_order[b * NQ + i] = (int)(s[i] & 0x3FFFu);
}

// per-lane edge/interior selection -> NEGATED (v,w)
__device__ __forceinline__ void lane_sel(
    float vb, float vc, float vbc, float den,
    float dab, float dac, float dbc,
    float nta, float ntb, float ntc,
    float nvi, float nwi, float& nv, float& nw)
{
    bool inside = (vb >= 0.0f) && (vc >= 0.0f) && (vbc <= den);
    bool pab = dab <= dac;
    float nve = pab ? nta : 0.0f;
    float nwe = pab ? 0.0f : ntb;
    float de = fminf(dab, dac);
    bool pbc = de <= dbc;
    float nvbc = -ntc - 1.0f;            // = -(1 - t_bc)
    nve = pbc ? nve : nvbc;
    nwe = pbc ? nwe : ntc;
    nv = inside ? nvi : nve;
    nw = inside ? nwi : nwe;
}

__device__ __forceinline__ void top2_upd(
    float dist, int t, float& best, int& bidx, float& best2, int& bidx2)
{
    bool lt1 = dist < best;
    bool lt2 = dist < best2;
    best2 = lt1 ? best : (lt2 ? dist : best2);
    bidx2 = lt1 ? bidx : (lt2 ? t    : bidx2);
    best  = lt1 ? dist : best;
    bidx  = lt1 ? t    : bidx;
}

// ---------------------------------------------------------------------------
// Kernel 1: scan with plane-distance lower-bound pruning (warp-uniform via
// Morton-sorted points + __any_sync). Eval body = R7 packed math (proven).
// Pruned triangles provably cannot enter the final top-2 (best2 monotone).
// ---------------------------------------------------------------------------
__global__ void __launch_bounds__(BLOCK, 6) k_main(const float* __restrict__ points) {
    __shared__ ulonglong2 sh[TILE_PAIRS * 10];
    __shared__ ulonglong2 sn[TILE_PAIRS * 2];
    int b = blockIdx.z;
    int qpos = blockIdx.x * BLOCK + threadIdx.x;
    int qi = g_order[b * NQ + qpos];
    const float* pp = points + (size_t)(b * NQ + qi) * 3;
    float px = pp[0], py = pp[1], pz = pp[2];
    u64 PX = f2pack(px, px), PY = f2pack(py, py), PZ = f2pack(pz, pz);
    int pairBase = blockIdx.y * PAIRS_PER_SPLIT;

    float best  = 3.402823e38f;  int bidx  = pairBase * 2;
    float best2 = 3.402823e38f;  int bidx2 = pairBase * 2;

    for (int tp0 = 0; tp0 < PAIRS_PER_SPLIT; tp0 += TILE_PAIRS) {
        __syncthreads();
        {
            const float4* src = g_tc2 + (size_t)(b * (NF/2) + pairBase + tp0) * 10;
            float4* dst = (float4*)sh;
            for (int i = threadIdx.x; i < TILE_PAIRS * 10; i += BLOCK) dst[i] = src[i];
            const float4* srcn = g_nr2 + (size_t)(b * (NF/2) + pairBase + tp0) * 2;
            float4* dstn = (float4*)sn;
            for (int i = threadIdx.x; i < TILE_PAIRS * 2; i += BLOCK) dstn[i] = srcn[i];
        }
        __syncthreads();

        for (int j = 0; j < TILE_PAIRS; j++) {
            // ---- plane-distance lower bound (2 triangles packed) ----
            ulonglong2 n0 = sn[j*2+0], n1 = sn[j*2+1];
            u64 LB = f2fma(n0.x, PX, f2fma(n0.y, PY, f2fma(n1.x, PZ, n1.y)));
            u64 LB2 = f2mul(LB, LB);
            float lb0, lb1;
            f2unpack(LB2, lb0, lb1);
            float thr2 = fmaf(best2, 1.002f, 1e-9f);
            bool interesting = (lb0 < thr2) || (lb1 < thr2);
            if (!__any_sync(0xFFFFFFFFu, interesting)) continue;

            const ulonglong2* tp = sh + j * 10;
            ulonglong2 s0 = tp[0], s1 = tp[1], s2 = tp[2], s3 = tp[3], s4 = tp[4];
            ulonglong2 s5 = tp[5], s6 = tp[6], s7 = tp[7], s8 = tp[8], s9 = tp[9];
            u64 NAX = s0.x, NAY = s0.y, NAZ = s1.x, ABX = s1.y;
            u64 ABY = s2.x, ABZ = s2.y, ACX = s3.x, ACY = s3.y;
            u64 ACZ = s4.x, AA  = s4.y, BB  = s5.x, NGG = s5.y;
            u64 NIA = s6.x, NIB = s6.y, NIC = s7.x, NID = s7.y;
            u64 AMG = s8.x, CB2 = s8.y, DEN = s9.x;

            u64 APX = f2add(PX, NAX);
            u64 APY = f2add(PY, NAY);
            u64 APZ = f2add(PZ, NAZ);

            u64 D1  = f2fma(ABX, APX, f2fma(ABY, APY, f2mul(ABZ, APZ)));
            u64 D2  = f2fma(ACX, APX, f2fma(ACY, APY, f2mul(ACZ, APZ)));
            u64 APP = f2fma(APX, APX, f2fma(APY, APY, f2mul(APZ, APZ)));

            u64 VC  = f2fma(AA, D2, f2mul(NGG, D1));
            u64 VB  = f2fma(BB, D1, f2mul(NGG, D2));
            u64 VBC = f2add(VB, VC);

            u64 NTAr = f2mul(D1, NIA);
            u64 NTBr = f2mul(D2, NIB);
            u64 ND1  = f2mul(D1, f2pack(-1.0f, -1.0f));
            u64 E1   = f2add(f2add(D2, ND1), AMG);
            u64 NTCr = f2mul(E1, NIC);
            float nta0, nta1, ntb0, ntb1, ntc0, ntc1;
            f2unpack(NTAr, nta0, nta1);
            f2unpack(NTBr, ntb0, ntb1);
            f2unpack(NTCr, ntc0, ntc1);
            nta0 = fmaxf(fminf(nta0, 0.0f), -1.0f);
            nta1 = fmaxf(fminf(nta1, 0.0f), -1.0f);
            ntb0 = fmaxf(fminf(ntb0, 0.0f), -1.0f);
            ntb1 = fmaxf(fminf(ntb1, 0.0f), -1.0f);
            ntc0 = fmaxf(fminf(ntc0, 0.0f), -1.0f);
            ntc1 = fmaxf(fminf(ntc1, 0.0f), -1.0f);
            u64 NTA = f2pack(nta0, nta1);
            u64 NTB = f2pack(ntb0, ntb1);
            u64 NTC = f2pack(ntc0, ntc1);

            u64 D1_2  = f2add(D1, D1);
            u64 ND1_2 = f2add(ND1, ND1);
            u64 DAB = f2fma(NTA, f2fma(NTA, AA, D1_2), APP);
            u64 D2_2  = f2add(D2, D2);
            u64 DAC = f2fma(NTB, f2fma(NTB, BB, D2_2), APP);
            u64 BP2 = f2add(f2add(APP, AA), ND1_2);
            u64 E1_2 = f2add(E1, E1);
            u64 DBC = f2fma(NTC, f2fma(NTC, CB2, E1_2), BP2);

            u64 NVI = f2mul(VB, NID);
            u64 NWI = f2mul(VC, NID);

            float vb0, vb1, vc0, vc1, vbc0, vbc1, den0, den1;
            float dab0, dab1, dac0, dac1, dbc0, dbc1, nvi0, nvi1, nwi0, nwi1;
            f2unpack(VB, vb0, vb1);   f2unpack(VC, vc0, vc1);
            f2unpack(VBC, vbc0, vbc1); f2unpack(DEN, den0, den1);
            f2unpack(DAB, dab0, dab1); f2unpack(DAC, dac0, dac1);
            f2unpack(DBC, dbc0, dbc1);
            f2unpack(NVI, nvi0, nvi1); f2unpack(NWI, nwi0, nwi1);

            float nv0, nw0, nv1, nw1;
            lane_sel(vb0, vc0, vbc0, den0, dab0, dac0, dbc0, nta0, ntb0, ntc0, nvi0, nwi0, nv0, nw0);
            lane_sel(vb1, vc1, vbc1, den1, dab1, dac1, dbc1, nta1, ntb1, ntc1, nvi1, nwi1, nv1, nw1);
            u64 NV = f2pack(nv0, nv1);
            u64 NW = f2pack(nw0, nw1);

            u64 DX = f2fma(NV, ABX, f2fma(NW, ACX, APX));
            u64 DY = f2fma(NV, ABY, f2fma(NW, ACY, APY));
            u64 DZ = f2fma(NV, ABZ, f2fma(NW, ACZ, APZ));
            u64 DIST = f2fma(DX, DX, f2fma(DY, DY, f2mul(DZ, DZ)));
            float dist0, dist1;
            f2unpack(DIST, dist0, dist1);

            int te = (pairBase + tp0 + j) * 2;
            top2_upd(dist0, te,     best, bidx, best2, bidx2);
            top2_upd(dist1, te + 1, best, bidx, best2, bidx2);
        }
    }

    g_cand[(size_t)(b * NQ + qi) * SPLITS + blockIdx.y] =
        make_uint2((unsigned)bidx, (unsigned)bidx2);
}

// ---------------------------------------------------------------------------
// Reference formula in DOUBLE precision (true-math ordering for arbitration).
// ---------------------------------------------------------------------------
__device__ void ref_eval_d(const float* __restrict__ tp,
                           double px, double py, double pz,
                           double& d2out, double& rxo, double& ryo, double& rzo) {
    double ax = tp[0], ay = tp[1], az = tp[2];
    double bx = tp[3], by = tp[4], bz = tp[5];
    double cx = tp[6], cy = tp[7], cz = tp[8];

    double abx = bx - ax, aby = by - ay, abz = bz - az;
    double acx = cx - ax, acy = cy - ay, acz = cz - az;
    double apx = px - ax, apy = py - ay, apz = pz - az;
    double d1 = abx*apx + aby*apy + abz*apz;
    double d2 = acx*apx + acy*apy + acz*apz;
    double bpx = px - bx, bpy = py - by, bpz = pz - bz;
    double d3 = abx*bpx + aby*bpy + abz*bpz;
    double d4 = acx*bpx + acy*bpy + acz*bpz;
    double cpx = px - cx, cpy = py - cy, cpz = pz - cz;
    double d5 = abx*cpx + aby*cpy + abz*cpz;
    double d6 = acx*cpx + acy*cpy + acz*cpz;

    double vc = d1*d4 - d3*d2;
    double vb = d5*d2 - d1*d6;
    double va = d3*d6 - d5*d4;
    double v_ab = dclamp01(dsafe_div(d1, d1 - d3));
    double w_ac = dclamp01(dsafe_div(d2, d2 - d6));
    double w_bc = dclamp01(dsafe_div(d4 - d3, (d4 - d3) + (d5 - d6)));
    double denom = va + vb + vc;
    double v = dsafe_div(vb, denom);
    double w = dsafe_div(vc, denom);

    double rx = ax + abx*v + acx*w;
    double ry = ay + aby*v + acy*w;
    double rz = az + abz*v + acz*w;

    bool m_bc = (va <= 0.0) && ((d4 - d3) >= 0.0) && ((d5 - d6) >= 0.0);
    if (m_bc) { rx = bx + w_bc*(cx - bx); ry = by + w_bc*(cy - by); rz = bz + w_bc*(cz - bz); }
    bool m_ac = (vb <= 0.0) && (d2 >= 0.0) && (d6 <= 0.0);
    if (m_ac) { rx = ax + w_ac*acx; ry = ay + w_ac*acy; rz = az + w_ac*acz; }
    bool m_ab = (vc <= 0.0) && (d1 >= 0.0) && (d3 <= 0.0);
    if (m_ab) { rx = ax + v_ab*abx; ry = ay + v_ab*aby; rz = az + v_ab*abz; }
    bool m_c = (d6 >= 0.0) && (d5 <= d6);
    if (m_c) { rx = cx; ry = cy; rz = cz; }
    bool m_b = (d3 >= 0.0) && (d4 <= d3);
    if (m_b) { rx = bx; ry = by; rz = bz; }
    bool m_a = (d1 <= 0.0) && (d2 <= 0.0);
    if (m_a) { rx = ax; ry = ay; rz = az; }

    double dxx = px - rx, dyy = py - ry, dzz = pz - rz;
    d2out = dxx*dxx + dyy*dyy + dzz*dzz;
    rxo = rx; ryo = ry; rzo = rz;
}

// ---------------------------------------------------------------------------
// Kernel 2: arbitrate the <=8 candidates per point in double precision, write
// outputs: dist[32768] | closest[32768*3] | faces[32768] (as float).
// ---------------------------------------------------------------------------
__global__ void k_fin(const float* __restrict__ tris,
                      const float* __restrict__ points,
                      float* __restrict__ out) {
    int i = blockIdx.x * blockDim.x + threadIdx.x;
    if (i >= NPTS) return;
    int b = i / NQ;

    const float* pp = points + (size_t)i * 3;
    double px = pp[0], py = pp[1], pz = pp[2];

    double bestD = 1e300, brx = 0, bry = 0, brz = 0;
    int bestI = 0x7FFFFFFF;

    #pragma unroll
    for (int s = 0; s < SPLITS; s++) {
        uint2 c = g_cand[(size_t)i * SPLITS + s];
        #pragma unroll
        for (int k = 0; k < 2; k++) {
            int idx = (k == 0) ? (int)c.x : (int)c.y;
            const float* tp = tris + (size_t)(b * NF + idx) * 9;
            double d2, rx, ry, rz;
            ref_eval_d(tp, px, py, pz, d2, rx, ry, rz);
            bool take = (d2 < bestD) || (d2 == bestD && idx < bestI);
            if (take) { bestD = d2; bestI = idx; brx = rx; bry = ry; brz = rz; }
        }
    }

    out[i] = (float)bestD;                               // distances [2,16384]
    out[NPTS + (size_t)i*3 + 0] = (float)brx;            // closest_points [2,16384,3]
    out[NPTS + (size_t)i*3 + 1] = (float)bry;
    out[NPTS + (size_t)i*3 + 2] = (float)brz;
    out[(size_t)NPTS*4 + i] = (float)bestI;              // closest_faces [2,16384]
}

extern "C" void kernel_launch(void* const* d_in, const int* in_sizes, int n_in,
                              void* d_out, int out_size) {
    const float* tris = (const float*)d_in[0];   // [2,4096,3,3]
    const float* pts  = (const float*)d_in[1];   // [2,16384,3]
    float* out = (float*)d_out;

    cudaFuncSetAttribute(k_sort, cudaFuncAttributeMaxDynamicSharedMemorySize, NQ * 4);

    k_pre<<<(NB*NF + 255) / 256, 256>>>(tris);
    k_sort<<<NB, 1024, NQ * 4>>>(pts);
    dim3 grid(NQ / BLOCK, SPLITS, NB);
    k_main<<<grid, BLOCK>>>(pts);
    k_fin<<<(NPTS + 255) / 256, 256>>>(tris, pts, out);
}

// round 9
// speedup vs baseline: 1.2821x; 1.2821x over previous
#include <cuda_runtime.h>
#include <math.h>

#define NB 2
#define NF 4096
#define NQ 16384
#define NPTS (NB*NQ)                  // 32768
#define BLOCK 128
#define PTS_PER_THREAD 2
#define SPLITS 8
#define TRIS_PER_SPLIT (NF/SPLITS)    // 512
#define PAIRS_PER_SPLIT (TRIS_PER_SPLIT/2)  // 256
#define TILE_PAIRS 128                // 256 triangles per smem tile, 20KB

typedef unsigned long long u64;

// Scratch (static __device__ arrays: allowed; no allocs anywhere)
__device__ float4 g_tc2[NB*(NF/2)*10];   // pair-interleaved eval consts
__device__ uint2  g_cand[NPTS*SPLITS];   // per (point,split): top-2 triangle indices

// ---- f32x2 packed helpers (sm_100a) ----
__device__ __forceinline__ u64 f2pack(float lo, float hi) {
    u64 r; asm("mov.b64 %0, {%1, %2};" : "=l"(r) : "f"(lo), "f"(hi)); return r;
}
__device__ __forceinline__ void f2unpack(u64 v, float& lo, float& hi) {
    asm("mov.b64 {%0, %1}, %2;" : "=f"(lo), "=f"(hi) : "l"(v));
}
__device__ __forceinline__ u64 f2add(u64 a, u64 b) {
    u64 r; asm("add.rn.f32x2 %0, %1, %2;" : "=l"(r) : "l"(a), "l"(b)); return r;
}
__device__ __forceinline__ u64 f2mul(u64 a, u64 b) {
    u64 r; asm("mul.rn.f32x2 %0, %1, %2;" : "=l"(r) : "l"(a), "l"(b)); return r;
}
__device__ __forceinline__ u64 f2fma(u64 a, u64 b, u64 c) {
    u64 r; asm("fma.rn.f32x2 %0, %1, %2, %3;" : "=l"(r) : "l"(a), "l"(b), "l"(c)); return r;
}

__device__ __forceinline__ float guard_inv(float x) {
    return (fabsf(x) > 1e-12f) ? (1.0f / x) : 1.0f;
}
__device__ __forceinline__ double dclamp01(double x) {
    return fmin(fmax(x, 0.0), 1.0);
}
__device__ __forceinline__ double dsafe_div(double num, double den) {
    double d = (fabs(den) > 1e-12) ? den : 1.0;
    return num / d;
}

// ---------------------------------------------------------------------------
// Kernel 0: per-triangle constants, pair-interleaved + pre-negated (R7 layout).
// ---------------------------------------------------------------------------
__global__ void k_pre(const float* __restrict__ tris) {
    int i = blockIdx.x * blockDim.x + threadIdx.x;
    if (i >= NB * NF) return;
    const float* t = tris + (size_t)i * 9;
    float ax = t[0], ay = t[1], az = t[2];
    float bx = t[3], by = t[4], bz = t[5];
    float cx = t[6], cy = t[7], cz = t[8];
    float abx = bx - ax, aby = by - ay, abz = bz - az;
    float acx = cx - ax, acy = cy - ay, acz = cz - az;
    float aa = abx*abx + aby*aby + abz*abz;
    float bb = acx*acx + acy*acy + acz*acz;
    float gg = abx*acx + aby*acy + abz*acz;
    float cb2 = aa + bb - 2.0f*gg;
    float den = aa*bb - gg*gg;

    int pi = i >> 1, lane = i & 1;
    float* o = ((float*)g_tc2) + (size_t)pi * 40 + lane;
    o[ 0] = -ax;  o[ 2] = -ay;  o[ 4] = -az;
    o[ 6] = abx;  o[ 8] = aby;  o[10] = abz;
    o[12] = acx;  o[14] = acy;  o[16] = acz;
    o[18] = aa;   o[20] = bb;   o[22] = -gg;
    o[24] = -guard_inv(aa);  o[26] = -guard_inv(bb);
    o[28] = -guard_inv(cb2); o[30] = -guard_inv(den);
    o[32] = aa - gg; o[34] = cb2; o[36] = den; o[38] = 0.0f;
}

// per-lane edge/interior selection -> NEGATED (v,w)
__device__ __forceinline__ void lane_sel(
    float vb, float vc, float vbc, float den,
    float dab, float dac, float dbc,
    float nta, float ntb, float ntc,
    float nvi, float nwi, float& nv, float& nw)
{
    bool inside = (vb >= 0.0f) && (vc >= 0.0f) && (vbc <= den);
    bool pab = dab <= dac;
    float nve = pab ? nta : 0.0f;
    float nwe = pab ? 0.0f : ntb;
    float de = fminf(dab, dac);
    bool pbc = de <= dbc;
    float nvbc = -ntc - 1.0f;            // = -(1 - t_bc)
    nve = pbc ? nve : nvbc;
    nwe = pbc ? nwe : ntc;
    nv = inside ? nvi : nve;
    nw = inside ? nwi : nwe;
}

__device__ __forceinline__ void top2_upd(
    float dist, int t, float& best, int& bidx, float& best2, int& bidx2)
{
    bool lt1 = dist < best;
    bool lt2 = dist < best2;
    best2 = lt1 ? best : (lt2 ? dist : best2);
    bidx2 = lt1 ? bidx : (lt2 ? t    : bidx2);
    best  = lt1 ? dist : best;
    bidx  = lt1 ? t    : bidx;
}

// Evaluate one packed triangle-pair against one point; update that point's top-2.
// (bitwise identical per lane to the R7 pipeline)
__device__ __forceinline__ void eval_pair(
    u64 PX, u64 PY, u64 PZ,
    u64 NAX, u64 NAY, u64 NAZ, u64 ABX, u64 ABY, u64 ABZ,
    u64 ACX, u64 ACY, u64 ACZ, u64 AA, u64 BB, u64 NGG,
    u64 NIA, u64 NIB, u64 NIC, u64 NID, u64 AMG, u64 CB2, u64 DEN,
    int te, float& best, int& bidx, float& best2, int& bidx2)
{
    u64 APX = f2add(PX, NAX);
    u64 APY = f2add(PY, NAY);
    u64 APZ = f2add(PZ, NAZ);

    u64 D1  = f2fma(ABX, APX, f2fma(ABY, APY, f2mul(ABZ, APZ)));
    u64 D2  = f2fma(ACX, APX, f2fma(ACY, APY, f2mul(ACZ, APZ)));
    u64 APP = f2fma(APX, APX, f2fma(APY, APY, f2mul(APZ, APZ)));

    u64 VC  = f2fma(AA, D2, f2mul(NGG, D1));
    u64 VB  = f2fma(BB, D1, f2mul(NGG, D2));
    u64 VBC = f2add(VB, VC);

    u64 NTAr = f2mul(D1, NIA);
    u64 NTBr = f2mul(D2, NIB);
    u64 ND1  = f2mul(D1, f2pack(-1.0f, -1.0f));
    u64 E1   = f2add(f2add(D2, ND1), AMG);
    u64 NTCr = f2mul(E1, NIC);
    float nta0, nta1, ntb0, ntb1, ntc0, ntc1;
    f2unpack(NTAr, nta0, nta1);
    f2unpack(NTBr, ntb0, ntb1);
    f2unpack(NTCr, ntc0, ntc1);
    nta0 = fmaxf(fminf(nta0, 0.0f), -1.0f);
    nta1 = fmaxf(fminf(nta1, 0.0f), -1.0f);
    ntb0 = fmaxf(fminf(ntb0, 0.0f), -1.0f);
    ntb1 = fmaxf(fminf(ntb1, 0.0f), -1.0f);
    ntc0 = fmaxf(fminf(ntc0, 0.0f), -1.0f);
    ntc1 = fmaxf(fminf(ntc1, 0.0f), -1.0f);
    u64 NTA = f2pack(nta0, nta1);
    u64 NTB = f2pack(ntb0, ntb1);
    u64 NTC = f2pack(ntc0, ntc1);

    u64 D1_2  = f2add(D1, D1);
    u64 ND1_2 = f2add(ND1, ND1);
    u64 DAB = f2fma(NTA, f2fma(NTA, AA, D1_2), APP);
    u64 D2_2  = f2add(D2, D2);
    u64 DAC = f2fma(NTB, f2fma(NTB, BB, D2_2), APP);
    u64 BP2 = f2add(f2add(APP, AA), ND1_2);
    u64 E1_2 = f2add(E1, E1);
    u64 DBC = f2fma(NTC, f2fma(NTC, CB2, E1_2), BP2);

    u64 NVI = f2mul(VB, NID);
    u64 NWI = f2mul(VC, NID);

    float vb0, vb1, vc0, vc1, vbc0, vbc1, den0, den1;
    float dab0, dab1, dac0, dac1, dbc0, dbc1, nvi0, nvi1, nwi0, nwi1;
    f2unpack(VB, vb0, vb1);   f2unpack(VC, vc0, vc1);
    f2unpack(VBC, vbc0, vbc1); f2unpack(DEN, den0, den1);
    f2unpack(DAB, dab0, dab1); f2unpack(DAC, dac0, dac1);
    f2unpack(DBC, dbc0, dbc1);
    f2unpack(NVI, nvi0, nvi1); f2unpack(NWI, nwi0, nwi1);

    float nv0, nw0, nv1, nw1;
    lane_sel(vb0, vc0, vbc0, den0, dab0, dac0, dbc0, nta0, ntb0, ntc0, nvi0, nwi0, nv0, nw0);
    lane_sel(vb1, vc1, vbc1, den1, dab1, dac1, dbc1, nta1, ntb1, ntc1, nvi1, nwi1, nv1, nw1);
    u64 NV = f2pack(nv0, nv1);
    u64 NW = f2pack(nw0, nw1);

    u64 DX = f2fma(NV, ABX, f2fma(NW, ACX, APX));
    u64 DY = f2fma(NV, ABY, f2fma(NW, ACY, APY));
    u64 DZ = f2fma(NV, ABZ, f2fma(NW, ACZ, APZ));
    u64 DIST = f2fma(DX, DX, f2fma(DY, DY, f2mul(DZ, DZ)));
    float dist0, dist1;
    f2unpack(DIST, dist0, dist1);

    top2_upd(dist0, te,     best, bidx, best2, bidx2);
    top2_upd(dist1, te + 1, best, bidx, best2, bidx2);
}

// ---------------------------------------------------------------------------
// Kernel 1: brute-force scan; 2 points per thread share each loaded triangle
// pair (halves LDS/loop overhead per point, doubles ILP). 8 splits keep the
// grid at 1024 blocks. Top-2 per (point, split); f64 arbitration downstream.
// ---------------------------------------------------------------------------
__global__ void __launch_bounds__(BLOCK, 4) k_main(const float* __restrict__ points) {
    __shared__ ulonglong2 sh[TILE_PAIRS * 10];
    int b = blockIdx.z;
    int q0 = blockIdx.x * (BLOCK * PTS_PER_THREAD) + threadIdx.x;
    int q1 = q0 + BLOCK;
    const float* pp0 = points + (size_t)(b * NQ + q0) * 3;
    const float* pp1 = points + (size_t)(b * NQ + q1) * 3;
    u64 PX0 = f2pack(pp0[0], pp0[0]), PY0 = f2pack(pp0[1], pp0[1]), PZ0 = f2pack(pp0[2], pp0[2]);
    u64 PX1 = f2pack(pp1[0], pp1[0]), PY1 = f2pack(pp1[1], pp1[1]), PZ1 = f2pack(pp1[2], pp1[2]);
    int pairBase = blockIdx.y * PAIRS_PER_SPLIT;

    float bestA  = 3.402823e38f;  int bidxA  = pairBase * 2;
    float bestA2 = 3.402823e38f;  int bidxA2 = pairBase * 2;
    float bestB  = 3.402823e38f;  int bidxB  = pairBase * 2;
    float bestB2 = 3.402823e38f;  int bidxB2 = pairBase * 2;

    for (int tp0 = 0; tp0 < PAIRS_PER_SPLIT; tp0 += TILE_PAIRS) {
        __syncthreads();
        {
            const float4* src = g_tc2 + (size_t)(b * (NF/2) + pairBase + tp0) * 10;
            float4* dst = (float4*)sh;
            for (int i = threadIdx.x; i < TILE_PAIRS * 10; i += BLOCK) dst[i] = src[i];
        }
        __syncthreads();

        #pragma unroll 2
        for (int j = 0; j < TILE_PAIRS; j++) {
            const ulonglong2* tp = sh + j * 10;
            ulonglong2 s0 = tp[0], s1 = tp[1], s2 = tp[2], s3 = tp[3], s4 = tp[4];
            ulonglong2 s5 = tp[5], s6 = tp[6], s7 = tp[7], s8 = tp[8], s9 = tp[9];
            u64 NAX = s0.x, NAY = s0.y, NAZ = s1.x, ABX = s1.y;
            u64 ABY = s2.x, ABZ = s2.y, ACX = s3.x, ACY = s3.y;
            u64 ACZ = s4.x, AA  = s4.y, BB  = s5.x, NGG = s5.y;
            u64 NIA = s6.x, NIB = s6.y, NIC = s7.x, NID = s7.y;
            u64 AMG = s8.x, CB2 = s8.y, DEN = s9.x;

            int te = (pairBase + tp0 + j) * 2;
            eval_pair(PX0, PY0, PZ0,
                      NAX, NAY, NAZ, ABX, ABY, ABZ, ACX, ACY, ACZ, AA, BB, NGG,
                      NIA, NIB, NIC, NID, AMG, CB2, DEN,
                      te, bestA, bidxA, bestA2, bidxA2);
            eval_pair(PX1, PY1, PZ1,
                      NAX, NAY, NAZ, ABX, ABY, ABZ, ACX, ACY, ACZ, AA, BB, NGG,
                      NIA, NIB, NIC, NID, AMG, CB2, DEN,
                      te, bestB, bidxB, bestB2, bidxB2);
        }
    }

    g_cand[(size_t)(b * NQ + q0) * SPLITS + blockIdx.y] =
        make_uint2((unsigned)bidxA, (unsigned)bidxA2);
    g_cand[(size_t)(b * NQ + q1) * SPLITS + blockIdx.y] =
        make_uint2((unsigned)bidxB, (unsigned)bidxB2);
}

// ---------------------------------------------------------------------------
// Reference formula in DOUBLE precision (true-math ordering for arbitration).
// ---------------------------------------------------------------------------
__device__ void ref_eval_d(const float* __restrict__ tp,
                           double px, double py, double pz,
                           double& d2out, double& rxo, double& ryo, double& rzo) {
    double ax = tp[0], ay = tp[1], az = tp[2];
    double bx = tp[3], by = tp[4], bz = tp[5];
    double cx = tp[6], cy = tp[7], cz = tp[8];

    double abx = bx - ax, aby = by - ay, abz = bz - az;
    double acx = cx - ax, acy = cy - ay, acz = cz - az;
    double apx = px - ax, apy = py - ay, apz = pz - az;
    double d1 = abx*apx + aby*apy + abz*apz;
    double d2 = acx*apx + acy*apy + acz*apz;
    double bpx = px - bx, bpy = py - by, bpz = pz - bz;
    double d3 = abx*bpx + aby*bpy + abz*bpz;
    double d4 = acx*bpx + acy*bpy + acz*bpz;
    double cpx = px - cx, cpy = py - cy, cpz = pz - cz;
    double d5 = abx*cpx + aby*cpy + abz*cpz;
    double d6 = acx*cpx + acy*cpy + acz*cpz;

    double vc = d1*d4 - d3*d2;
    double vb = d5*d2 - d1*d6;
    double va = d3*d6 - d5*d4;
    double v_ab = dclamp01(dsafe_div(d1, d1 - d3));
    double w_ac = dclamp01(dsafe_div(d2, d2 - d6));
    double w_bc = dclamp01(dsafe_div(d4 - d3, (d4 - d3) + (d5 - d6)));
    double denom = va + vb + vc;
    double v = dsafe_div(vb, denom);
    double w = dsafe_div(vc, denom);

    double rx = ax + abx*v + acx*w;
    double ry = ay + aby*v + acy*w;
    double rz = az + abz*v + acz*w;

    bool m_bc = (va <= 0.0) && ((d4 - d3) >= 0.0) && ((d5 - d6) >= 0.0);
    if (m_bc) { rx = bx + w_bc*(cx - bx); ry = by + w_bc*(cy - by); rz = bz + w_bc*(cz - bz); }
    bool m_ac = (vb <= 0.0) && (d2 >= 0.0) && (d6 <= 0.0);
    if (m_ac) { rx = ax + w_ac*acx; ry = ay + w_ac*acy; rz = az + w_ac*acz; }
    bool m_ab = (vc <= 0.0) && (d1 >= 0.0) && (d3 <= 0.0);
    if (m_ab) { rx = ax + v_ab*abx; ry = ay + v_ab*aby; rz = az + v_ab*abz; }
    bool m_c = (d6 >= 0.0) && (d5 <= d6);
    if (m_c) { rx = cx; ry = cy; rz = cz; }
    bool m_b = (d3 >= 0.0) && (d4 <= d3);
    if (m_b) { rx = bx; ry = by; rz = bz; }
    bool m_a = (d1 <= 0.0) && (d2 <= 0.0);
    if (m_a) { rx = ax; ry = ay; rz = az; }

    double dxx = px - rx, dyy = py - ry, dzz = pz - rz;
    d2out = dxx*dxx + dyy*dyy + dzz*dzz;
    rxo = rx; ryo = ry; rzo = rz;
}

// ---------------------------------------------------------------------------
// Kernel 2: arbitrate the <=16 candidates per point in double precision, write
// outputs: dist[32768] | closest[32768*3] | faces[32768] (as float).
// ---------------------------------------------------------------------------
__global__ void k_fin(const float* __restrict__ tris,
                      const float* __restrict__ points,
                      float* __restrict__ out) {
    int i = blockIdx.x * blockDim.x + threadIdx.x;
    if (i >= NPTS) return;
    int b = i / NQ;

    const float* pp = points + (size_t)i * 3;
    double px = pp[0], py = pp[1], pz = pp[2];

    double bestD = 1e300, brx = 0, bry = 0, brz = 0;
    int bestI = 0x7FFFFFFF;

    #pragma unroll
    for (int s = 0; s < SPLITS; s++) {
        uint2 c = g_cand[(size_t)i * SPLITS + s];
        #pragma unroll
        for (int k = 0; k < 2; k++) {
            int idx = (k == 0) ? (int)c.x : (int)c.y;
            const float* tp = tris + (size_t)(b * NF + idx) * 9;
            double d2, rx, ry, rz;
            ref_eval_d(tp, px, py, pz, d2, rx, ry, rz);
            bool take = (d2 < bestD) || (d2 == bestD && idx < bestI);
            if (take) { bestD = d2; bestI = idx; brx = rx; bry = ry; brz = rz; }
        }
    }

    out[i] = (float)bestD;                               // distances [2,16384]
    out[NPTS + (size_t)i*3 + 0] = (float)brx;            // closest_points [2,16384,3]
    out[NPTS + (size_t)i*3 + 1] = (float)bry;
    out[NPTS + (size_t)i*3 + 2] = (float)brz;
    out[(size_t)NPTS*4 + i] = (float)bestI;              // closest_faces [2,16384]
}

extern "C" void kernel_launch(void* const* d_in, const int* in_sizes, int n_in,
                              void* d_out, int out_size) {
    const float* tris = (const float*)d_in[0];   // [2,4096,3,3]
    const float* pts  = (const float*)d_in[1];   // [2,16384,3]
    float* out = (float*)d_out;

    k_pre<<<(NB*NF + 255) / 256, 256>>>(tris);
    dim3 grid(NQ / (BLOCK * PTS_PER_THREAD), SPLITS, NB);
    k_main<<<grid, BLOCK>>>(pts);
    k_fin<<<(NPTS + 255) / 256, 256>>>(tris, pts, out);
}

// round 11
// speedup vs baseline: 1.3050x; 1.0179x over previous
#include <cuda_runtime.h>
#include <math.h>

#define NB 2
#define NF 4096
#define NQ 16384
#define NPTS (NB*NQ)                  // 32768
#define BLOCK 128
#define SPLITS 4
#define TRIS_PER_SPLIT (NF/SPLITS)    // 1024
#define PAIRS_PER_SPLIT (TRIS_PER_SPLIT/2)  // 512
#define TILE_PAIRS 128                // 256 triangles per smem tile, 20KB

typedef unsigned long long u64;

// Scratch (static __device__ arrays: allowed; no allocs anywhere)
__device__ float4 g_tc2[NB*(NF/2)*10];   // pair-interleaved consts: 10 x float4 per tri-pair
__device__ uint2  g_cand[NPTS*SPLITS];   // per (point,split): top-2 triangle indices

// ---- f32x2 packed helpers (sm_100a; add/mul/fma only — min/max unsupported) ----
__device__ __forceinline__ u64 f2pack(float lo, float hi) {
    u64 r; asm("mov.b64 %0, {%1, %2};" : "=l"(r) : "f"(lo), "f"(hi)); return r;
}
__device__ __forceinline__ void f2unpack(u64 v, float& lo, float& hi) {
    asm("mov.b64 {%0, %1}, %2;" : "=f"(lo), "=f"(hi) : "l"(v));
}
__device__ __forceinline__ u64 f2add(u64 a, u64 b) {
    u64 r; asm("add.rn.f32x2 %0, %1, %2;" : "=l"(r) : "l"(a), "l"(b)); return r;
}
__device__ __forceinline__ u64 f2mul(u64 a, u64 b) {
    u64 r; asm("mul.rn.f32x2 %0, %1, %2;" : "=l"(r) : "l"(a), "l"(b)); return r;
}
__device__ __forceinline__ u64 f2fma(u64 a, u64 b, u64 c) {
    u64 r; asm("fma.rn.f32x2 %0, %1, %2, %3;" : "=l"(r) : "l"(a), "l"(b), "l"(c)); return r;
}
// scalar multiply with saturate-to-[0,1] folded in (1 SASS op)
__device__ __forceinline__ float fmul_sat(float a, float b) {
    float r; asm("mul.rn.sat.f32 %0, %1, %2;" : "=f"(r) : "f"(a), "f"(b)); return r;
}

__device__ __forceinline__ float guard_inv(float x) {
    return (fabsf(x) > 1e-12f) ? (1.0f / x) : 1.0f;
}
__device__ __forceinline__ double dclamp01(double x) {
    return fmin(fmax(x, 0.0), 1.0);
}
__device__ __forceinline__ double dsafe_div(double num, double den) {
    double d = (fabs(den) > 1e-12) ? den : 1.0;
    return num / d;
}

// ---------------------------------------------------------------------------
// Kernel 0: per-triangle constants, pair-interleaved. POSITIVE reciprocals
// (saturate convention). Slots per tri (stored as {even,odd} float pairs):
//  0:-ax 1:-ay 2:-az 3:abx 4:aby 5:abz 6:acx 7:acy 8:acz 9:aa
// 10:bb 11:-gg 12:+1/aa 13:+1/bb 14:+1/cb2 15:+1/den 16:aa-gg 17:cb2 18:den 19:pad
// ---------------------------------------------------------------------------
__global__ void k_pre(const float* __restrict__ tris) {
    int i = blockIdx.x * blockDim.x + threadIdx.x;
    if (i >= NB * NF) return;
    const float* t = tris + (size_t)i * 9;
    float ax = t[0], ay = t[1], az = t[2];
    float bx = t[3], by = t[4], bz = t[5];
    float cx = t[6], cy = t[7], cz = t[8];
    float abx = bx - ax, aby = by - ay, abz = bz - az;
    float acx = cx - ax, acy = cy - ay, acz = cz - az;
    float aa = abx*abx + aby*aby + abz*abz;
    float bb = acx*acx + acy*acy + acz*acz;
    float gg = abx*acx + aby*acy + abz*acz;
    float cb2 = aa + bb - 2.0f*gg;
    float den = aa*bb - gg*gg;

    int pi = i >> 1, lane = i & 1;
    float* o = ((float*)g_tc2) + (size_t)pi * 40 + lane;
    o[ 0] = -ax;  o[ 2] = -ay;  o[ 4] = -az;
    o[ 6] = abx;  o[ 8] = aby;  o[10] = abz;
    o[12] = acx;  o[14] = acy;  o[16] = acz;
    o[18] = aa;   o[20] = bb;   o[22] = -gg;
    o[24] = guard_inv(aa);  o[26] = guard_inv(bb);
    o[28] = guard_inv(cb2); o[30] = guard_inv(den);
    o[32] = aa - gg; o[34] = cb2; o[36] = den; o[38] = 0.0f;
}

// per-lane edge/interior selection -> POSITIVE (v,w)
__device__ __forceinline__ void lane_sel(
    float vb, float vc, float vbc, float den,
    float dab, float dac, float dbc,
    float ta, float tb, float tc,
    float vi, float wi, float& v, float& w)
{
    bool inside = (vb >= 0.0f) && (vc >= 0.0f) && (vbc <= den);
    bool pab = dab <= dac;
    float ve = pab ? ta : 0.0f;
    float we = pab ? 0.0f : tb;
    float de = fminf(dab, dac);
    bool pbc = de <= dbc;
    float vbcv = 1.0f - tc;
    ve = pbc ? ve : vbcv;
    we = pbc ? we : tc;
    v = inside ? vi : ve;
    w = inside ? wi : we;
}

__device__ __forceinline__ void top2_upd(
    float dist, int t, float& best, int& bidx, float& best2, int& bidx2)
{
    bool lt1 = dist < best;
    bool lt2 = dist < best2;
    best2 = lt1 ? best : (lt2 ? dist : best2);
    bidx2 = lt1 ? bidx : (lt2 ? t    : bidx2);
    best  = lt1 ? dist : best;
    bidx  = lt1 ? t    : bidx;
}

// ---------------------------------------------------------------------------
// Kernel 1: brute-force scan, 2 triangles/iter packed in f32x2 lanes.
// Clamps via scalar mul.rn.sat (1 op each); final (v,w) negated by exact
// *(-1) so DX/DY/DZ/DIST are bitwise identical to the proven R7 pipeline.
// Top-2 per split; f64 arbitration downstream.
// ---------------------------------------------------------------------------
__global__ void __launch_bounds__(BLOCK, 7) k_main(const float* __restrict__ points) {
    __shared__ ulonglong2 sh[TILE_PAIRS * 10];
    int b = blockIdx.z;
    int q = blockIdx.x * BLOCK + threadIdx.x;
    const float* pp = points + (size_t)(b * NQ + q) * 3;
    float px = pp[0], py = pp[1], pz = pp[2];
    u64 PX = f2pack(px, px), PY = f2pack(py, py), PZ = f2pack(pz, pz);
    const u64 KN1 = f2pack(-1.0f, -1.0f);
    int pairBase = blockIdx.y * PAIRS_PER_SPLIT;

    float best  = 3.402823e38f;  int bidx  = pairBase * 2;
    float best2 = 3.402823e38f;  int bidx2 = pairBase * 2;

    for (int tp0 = 0; tp0 < PAIRS_PER_SPLIT; tp0 += TILE_PAIRS) {
        __syncthreads();
        {
            const float4* src = g_tc2 + (size_t)(b * (NF/2) + pairBase + tp0) * 10;
            float4* dst = (float4*)sh;
            #pragma unroll
            for (int i = threadIdx.x; i < TILE_PAIRS * 10; i += BLOCK) dst[i] = src[i];
        }
        __syncthreads();

        #pragma unroll 4
        for (int j = 0; j < TILE_PAIRS; j++) {
            const ulonglong2* tp = sh + j * 10;
            ulonglong2 s0 = tp[0], s1 = tp[1], s2 = tp[2], s3 = tp[3], s4 = tp[4];
            ulonglong2 s5 = tp[5], s6 = tp[6], s7 = tp[7], s8 = tp[8], s9 = tp[9];
            u64 NAX = s0.x, NAY = s0.y, NAZ = s1.x, ABX = s1.y;
            u64 ABY = s2.x, ABZ = s2.y, ACX = s3.x, ACY = s3.y;
            u64 ACZ = s4.x, AA  = s4.y, BB  = s5.x, NGG = s5.y;
            u64 IA  = s6.x, IB  = s6.y, IC  = s7.x, ID  = s7.y;
            u64 AMG = s8.x, CB2 = s8.y, DEN = s9.x;

            u64 APX = f2add(PX, NAX);
            u64 APY = f2add(PY, NAY);
            u64 APZ = f2add(PZ, NAZ);

            u64 D1  = f2fma(ABX, APX, f2fma(ABY, APY, f2mul(ABZ, APZ)));
            u64 D2  = f2fma(ACX, APX, f2fma(ACY, APY, f2mul(ACZ, APZ)));
            u64 APP = f2fma(APX, APX, f2fma(APY, APY, f2mul(APZ, APZ)));

            u64 VC  = f2fma(AA, D2, f2mul(NGG, D1));
            u64 VB  = f2fma(BB, D1, f2mul(NGG, D2));
            u64 VBC = f2add(VB, VC);

            // edge parameter numerator for BC:  e1 = (d2 - d1) + (aa - gg)
            u64 E1 = f2add(f2fma(KN1, D1, D2), AMG);

            // clamped edge params via scalar saturate-multiplies (positive t)
            float d1l0, d1l1, d2l0, d2l1, e1l0, e1l1;
            f2unpack(D1, d1l0, d1l1);
            f2unpack(D2, d2l0, d2l1);
            f2unpack(E1, e1l0, e1l1);
            float ia0, ia1, ib0, ib1, ic0, ic1;
            f2unpack(IA, ia0, ia1);
            f2unpack(IB, ib0, ib1);
            f2unpack(IC, ic0, ic1);
            float ta0 = fmul_sat(d1l0, ia0), ta1 = fmul_sat(d1l1, ia1);
            float tb0 = fmul_sat(d2l0, ib0), tb1 = fmul_sat(d2l1, ib1);
            float tc0 = fmul_sat(e1l0, ic0), tc1 = fmul_sat(e1l1, ic1);
            u64 TA = f2pack(ta0, ta1);
            u64 TB = f2pack(tb0, tb1);
            u64 TC = f2pack(tc0, tc1);

            // scalar edge distances (selection only), packed arithmetic.
            // inner terms sign-mirrored vs R7 -> bitwise-equal outer results.
            u64 D1_2  = f2add(D1, D1);
            u64 ND1_2 = f2mul(D1_2, KN1);
            u64 DAB = f2fma(TA, f2fma(TA, AA, ND1_2), APP);
            u64 ND2_2 = f2mul(f2add(D2, D2), KN1);
            u64 DAC = f2fma(TB, f2fma(TB, BB, ND2_2), APP);
            u64 BP2 = f2add(f2add(APP, AA), ND1_2);
            u64 NE1_2 = f2mul(f2add(E1, E1), KN1);
            u64 DBC = f2fma(TC, f2fma(TC, CB2, NE1_2), BP2);

            u64 VI = f2mul(VB, ID);
            u64 WI = f2mul(VC, ID);

            float vb0, vb1, vc0, vc1, vbc0, vbc1, den0, den1;
            float dab0, dab1, dac0, dac1, dbc0, dbc1, vi0, vi1, wi0, wi1;
            f2unpack(VB, vb0, vb1);    f2unpack(VC, vc0, vc1);
            f2unpack(VBC, vbc0, vbc1); f2unpack(DEN, den0, den1);
            f2unpack(DAB, dab0, dab1); f2unpack(DAC, dac0, dac1);
            f2unpack(DBC, dbc0, dbc1);
            f2unpack(VI, vi0, vi1);    f2unpack(WI, wi0, wi1);

            float v0, w0, v1, w1;
            lane_sel(vb0, vc0, vbc0, den0, dab0, dac0, dbc0, ta0, tb0, tc0, vi0, wi0, v0, w0);
            lane_sel(vb1, vc1, vbc1, den1, dab1, dac1, dbc1, ta1, tb1, tc1, vi1, wi1, v1, w1);

            // exact negation -> distance pipeline bitwise == R7
            u64 NV = f2mul(f2pack(v0, v1), KN1);
            u64 NW = f2mul(f2pack(w0, w1), KN1);

            u64 DX = f2fma(NV, ABX, f2fma(NW, ACX, APX));
            u64 DY = f2fma(NV, ABY, f2fma(NW, ACY, APY));
            u64 DZ = f2fma(NV, ABZ, f2fma(NW, ACZ, APZ));
            u64 DIST = f2fma(DX, DX, f2fma(DY, DY, f2mul(DZ, DZ)));
            float dist0, dist1;
            f2unpack(DIST, dist0, dist1);

            int te = (pairBase + tp0 + j) * 2;
            top2_upd(dist0, te,     best, bidx, best2, bidx2);
            top2_upd(dist1, te + 1, best, bidx, best2, bidx2);
        }
    }

    g_cand[(size_t)(b * NQ + q) * SPLITS + blockIdx.y] =
        make_uint2((unsigned)bidx, (unsigned)bidx2);
}

// ---------------------------------------------------------------------------
// Reference formula in DOUBLE precision (true-math ordering for arbitration).
// ---------------------------------------------------------------------------
__device__ void ref_eval_d(const float* __restrict__ tp,
                           double px, double py, double pz,
                           double& d2out, double& rxo, double& ryo, double& rzo) {
    double ax = tp[0], ay = tp[1], az = tp[2];
    double bx = tp[3], by = tp[4], bz = tp[5];
    double cx = tp[6], cy = tp[7], cz = tp[8];

    double abx = bx - ax, aby = by - ay, abz = bz - az;
    double acx = cx - ax, acy = cy - ay, acz = cz - az;
    double apx = px - ax, apy = py - ay, apz = pz - az;
    double d1 = abx*apx + aby*apy + abz*apz;
    double d2 = acx*apx + acy*apy + acz*apz;
    double bpx = px - bx, bpy = py - by, bpz = pz - bz;
    double d3 = abx*bpx + aby*bpy + abz*bpz;
    double d4 = acx*bpx + acy*bpy + acz*bpz;
    double cpx = px - cx, cpy = py - cy, cpz = pz - cz;
    double d5 = abx*cpx + aby*cpy + abz*cpz;
    double d6 = acx*cpx + acy*cpy + acz*cpz;

    double vc = d1*d4 - d3*d2;
    double vb = d5*d2 - d1*d6;
    double va = d3*d6 - d5*d4;
    double v_ab = dclamp01(dsafe_div(d1, d1 - d3));
    double w_ac = dclamp01(dsafe_div(d2, d2 - d6));
    double w_bc = dclamp01(dsafe_div(d4 - d3, (d4 - d3) + (d5 - d6)));
    double denom = va + vb + vc;
    double v = dsafe_div(vb, denom);
    double w = dsafe_div(vc, denom);

    double rx = ax + abx*v + acx*w;
    double ry = ay + aby*v + acy*w;
    double rz = az + abz*v + acz*w;

    bool m_bc = (va <= 0.0) && ((d4 - d3) >= 0.0) && ((d5 - d6) >= 0.0);
    if (m_bc) { rx = bx + w_bc*(cx - bx); ry = by + w_bc*(cy - by); rz = bz + w_bc*(cz - bz); }
    bool m_ac = (vb <= 0.0) && (d2 >= 0.0) && (d6 <= 0.0);
    if (m_ac) { rx = ax + w_ac*acx; ry = ay + w_ac*acy; rz = az + w_ac*acz; }
    bool m_ab = (vc <= 0.0) && (d1 >= 0.0) && (d3 <= 0.0);
    if (m_ab) { rx = ax + v_ab*abx; ry = ay + v_ab*aby; rz = az + v_ab*abz; }
    bool m_c = (d6 >= 0.0) && (d5 <= d6);
    if (m_c) { rx = cx; ry = cy; rz = cz; }
    bool m_b = (d3 >= 0.0) && (d4 <= d3);
    if (m_b) { rx = bx; ry = by; rz = bz; }
    bool m_a = (d1 <= 0.0) && (d2 <= 0.0);
    if (m_a) { rx = ax; ry = ay; rz = az; }

    double dxx = px - rx, dyy = py - ry, dzz = pz - rz;
    d2out = dxx*dxx + dyy*dyy + dzz*dzz;
    rxo = rx; ryo = ry; rzo = rz;
}

// ---------------------------------------------------------------------------
// Kernel 2: arbitrate the <=8 candidates per point in double precision, write
// outputs: dist[32768] | closest[32768*3] | faces[32768] (as float).
// ---------------------------------------------------------------------------
__global__ void k_fin(const float* __restrict__ tris,
                      const float* __restrict__ points,
                      float* __restrict__ out) {
    int i = blockIdx.x * blockDim.x + threadIdx.x;
    if (i >= NPTS) return;
    int b = i / NQ;

    const float* pp = points + (size_t)i * 3;
    double px = pp[0], py = pp[1], pz = pp[2];

    double bestD = 1e300, brx = 0, bry = 0, brz = 0;
    int bestI = 0x7FFFFFFF;

    #pragma unroll
    for (int s = 0; s < SPLITS; s++) {
        uint2 c = g_cand[(size_t)i * SPLITS + s];
        #pragma unroll
        for (int k = 0; k < 2; k++) {
            int idx = (k == 0) ? (int)c.x : (int)c.y;
            const float* tp = tris + (size_t)(b * NF + idx) * 9;
            double d2, rx, ry, rz;
            ref_eval_d(tp, px, py, pz, d2, rx, ry, rz);
            bool take = (d2 < bestD) || (d2 == bestD && idx < bestI);
            if (take) { bestD = d2; bestI = idx; brx = rx; bry = ry; brz = rz; }
        }
    }

    out[i] = (float)bestD;                               // distances [2,16384]
    out[NPTS + (size_t)i*3 + 0] = (float)brx;            // closest_points [2,16384,3]
    out[NPTS + (size_t)i*3 + 1] = (float)bry;
    out[NPTS + (size_t)i*3 + 2] = (float)brz;
    out[(size_t)NPTS*4 + i] = (float)bestI;              // closest_faces [2,16384]
}

extern "C" void kernel_launch(void* const* d_in, const int* in_sizes, int n_in,
                              void* d_out, int out_size) {
    const float* tris = (const float*)d_in[0];   // [2,4096,3,3]
    const float* pts  = (const float*)d_in[1];   // [2,16384,3]
    float* out = (float*)d_out;

    k_pre<<<(NB*NF + 255) / 256, 256>>>(tris);
    dim3 grid(NQ / BLOCK, SPLITS, NB);
    k_main<<<grid, BLOCK>>>(pts);
    k_fin<<<(NPTS + 255) / 256, 256>>>(tris, pts, out);
}

// round 12
// speedup vs baseline: 1.3716x; 1.0510x over previous
#include <cuda_runtime.h>
#include <math.h>

#define NB 2
#define NF 4096
#define NQ 16384
#define NPTS (NB*NQ)                  // 32768
#define BLOCK 128
#define PTS_PER_THREAD 2
#define SPLITS 8
#define TRIS_PER_SPLIT (NF/SPLITS)    // 512
#define PAIRS_PER_SPLIT (TRIS_PER_SPLIT/2)  // 256
#define TILE_PAIRS 128                // 256 triangles per smem tile, 20KB

typedef unsigned long long u64;

// Scratch (static __device__ arrays: allowed; no allocs anywhere)
__device__ float4 g_tc2[NB*(NF/2)*10];   // pair-interleaved consts: 10 x float4 per tri-pair
__device__ uint2  g_cand[NPTS*SPLITS];   // per (point,split): top-2 triangle indices

// ---- f32x2 packed helpers (sm_100a; add/mul/fma only) ----
__device__ __forceinline__ u64 f2pack(float lo, float hi) {
    u64 r; asm("mov.b64 %0, {%1, %2};" : "=l"(r) : "f"(lo), "f"(hi)); return r;
}
__device__ __forceinline__ void f2unpack(u64 v, float& lo, float& hi) {
    asm("mov.b64 {%0, %1}, %2;" : "=f"(lo), "=f"(hi) : "l"(v));
}
__device__ __forceinline__ u64 f2add(u64 a, u64 b) {
    u64 r; asm("add.rn.f32x2 %0, %1, %2;" : "=l"(r) : "l"(a), "l"(b)); return r;
}
__device__ __forceinline__ u64 f2mul(u64 a, u64 b) {
    u64 r; asm("mul.rn.f32x2 %0, %1, %2;" : "=l"(r) : "l"(a), "l"(b)); return r;
}
__device__ __forceinline__ u64 f2fma(u64 a, u64 b, u64 c) {
    u64 r; asm("fma.rn.f32x2 %0, %1, %2, %3;" : "=l"(r) : "l"(a), "l"(b), "l"(c)); return r;
}
// scalar multiply with saturate-to-[0,1] folded in
__device__ __forceinline__ float fmul_sat(float a, float b) {
    float r; asm("mul.rn.sat.f32 %0, %1, %2;" : "=f"(r) : "f"(a), "f"(b)); return r;
}

__device__ __forceinline__ float guard_inv(float x) {
    return (fabsf(x) > 1e-12f) ? (1.0f / x) : 1.0f;
}
__device__ __forceinline__ double dclamp01(double x) {
    return fmin(fmax(x, 0.0), 1.0);
}
__device__ __forceinline__ double dsafe_div(double num, double den) {
    double d = (fabs(den) > 1e-12) ? den : 1.0;
    return num / d;
}

// ---------------------------------------------------------------------------
// Kernel 0: per-triangle constants, pair-interleaved, POSITIVE reciprocals
// (R11 layout, proven).
// ---------------------------------------------------------------------------
__global__ void k_pre(const float* __restrict__ tris) {
    int i = blockIdx.x * blockDim.x + threadIdx.x;
    if (i >= NB * NF) return;
    const float* t = tris + (size_t)i * 9;
    float ax = t[0], ay = t[1], az = t[2];
    float bx = t[3], by = t[4], bz = t[5];
    float cx = t[6], cy = t[7], cz = t[8];
    float abx = bx - ax, aby = by - ay, abz = bz - az;
    float acx = cx - ax, acy = cy - ay, acz = cz - az;
    float aa = abx*abx + aby*aby + abz*abz;
    float bb = acx*acx + acy*acy + acz*acz;
    float gg = abx*acx + aby*acy + abz*acz;
    float cb2 = aa + bb - 2.0f*gg;
    float den = aa*bb - gg*gg;

    int pi = i >> 1, lane = i & 1;
    float* o = ((float*)g_tc2) + (size_t)pi * 40 + lane;
    o[ 0] = -ax;  o[ 2] = -ay;  o[ 4] = -az;
    o[ 6] = abx;  o[ 8] = aby;  o[10] = abz;
    o[12] = acx;  o[14] = acy;  o[16] = acz;
    o[18] = aa;   o[20] = bb;   o[22] = -gg;
    o[24] = guard_inv(aa);  o[26] = guard_inv(bb);
    o[28] = guard_inv(cb2); o[30] = guard_inv(den);
    o[32] = aa - gg; o[34] = cb2; o[36] = den; o[38] = 0.0f;
}

// per-lane edge/interior selection -> POSITIVE (v,w)
__device__ __forceinline__ void lane_sel(
    float vb, float vc, float vbc, float den,
    float dab, float dac, float dbc,
    float ta, float tb, float tc,
    float vi, float wi, float& v, float& w)
{
    bool inside = (vb >= 0.0f) && (vc >= 0.0f) && (vbc <= den);
    bool pab = dab <= dac;
    float ve = pab ? ta : 0.0f;
    float we = pab ? 0.0f : tb;
    float de = fminf(dab, dac);
    bool pbc = de <= dbc;
    float vbcv = 1.0f - tc;
    ve = pbc ? ve : vbcv;
    we = pbc ? we : tc;
    v = inside ? vi : ve;
    w = inside ? wi : we;
}

__device__ __forceinline__ void top2_upd(
    float dist, int t, float& best, int& bidx, float& best2, int& bidx2)
{
    bool lt1 = dist < best;
    bool lt2 = dist < best2;
    best2 = lt1 ? best : (lt2 ? dist : best2);
    bidx2 = lt1 ? bidx : (lt2 ? t    : bidx2);
    best  = lt1 ? dist : best;
    bidx  = lt1 ? t    : bidx;
}

// Evaluate one packed triangle-pair against one point (R11 sat-clamp body;
// distance pipeline bitwise == proven R7/R11).
__device__ __forceinline__ void eval_pair(
    u64 PX, u64 PY, u64 PZ, u64 KN1,
    u64 NAX, u64 NAY, u64 NAZ, u64 ABX, u64 ABY, u64 ABZ,
    u64 ACX, u64 ACY, u64 ACZ, u64 AA, u64 BB, u64 NGG,
    u64 IA, u64 IB, u64 IC, u64 ID, u64 AMG, u64 CB2, u64 DEN,
    int te, float& best, int& bidx, float& best2, int& bidx2)
{
    u64 APX = f2add(PX, NAX);
    u64 APY = f2add(PY, NAY);
    u64 APZ = f2add(PZ, NAZ);

    u64 D1  = f2fma(ABX, APX, f2fma(ABY, APY, f2mul(ABZ, APZ)));
    u64 D2  = f2fma(ACX, APX, f2fma(ACY, APY, f2mul(ACZ, APZ)));
    u64 APP = f2fma(APX, APX, f2fma(APY, APY, f2mul(APZ, APZ)));

    u64 VC  = f2fma(AA, D2, f2mul(NGG, D1));
    u64 VB  = f2fma(BB, D1, f2mul(NGG, D2));
    u64 VBC = f2add(VB, VC);

    u64 E1 = f2add(f2fma(KN1, D1, D2), AMG);

    float d1l0, d1l1, d2l0, d2l1, e1l0, e1l1;
    f2unpack(D1, d1l0, d1l1);
    f2unpack(D2, d2l0, d2l1);
    f2unpack(E1, e1l0, e1l1);
    float ia0, ia1, ib0, ib1, ic0, ic1;
    f2unpack(IA, ia0, ia1);
    f2unpack(IB, ib0, ib1);
    f2unpack(IC, ic0, ic1);
    float ta0 = fmul_sat(d1l0, ia0), ta1 = fmul_sat(d1l1, ia1);
    float tb0 = fmul_sat(d2l0, ib0), tb1 = fmul_sat(d2l1, ib1);
    float tc0 = fmul_sat(e1l0, ic0), tc1 = fmul_sat(e1l1, ic1);
    u64 TA = f2pack(ta0, ta1);
    u64 TB = f2pack(tb0, tb1);
    u64 TC = f2pack(tc0, tc1);

    u64 D1_2  = f2add(D1, D1);
    u64 ND1_2 = f2mul(D1_2, KN1);
    u64 DAB = f2fma(TA, f2fma(TA, AA, ND1_2), APP);
    u64 ND2_2 = f2mul(f2add(D2, D2), KN1);
    u64 DAC = f2fma(TB, f2fma(TB, BB, ND2_2), APP);
    u64 BP2 = f2add(f2add(APP, AA), ND1_2);
    u64 NE1_2 = f2mul(f2add(E1, E1), KN1);
    u64 DBC = f2fma(TC, f2fma(TC, CB2, NE1_2), BP2);

    u64 VI = f2mul(VB, ID);
    u64 WI = f2mul(VC, ID);

    float vb0, vb1, vc0, vc1, vbc0, vbc1, den0, den1;
    float dab0, dab1, dac0, dac1, dbc0, dbc1, vi0, vi1, wi0, wi1;
    f2unpack(VB, vb0, vb1);    f2unpack(VC, vc0, vc1);
    f2unpack(VBC, vbc0, vbc1); f2unpack(DEN, den0, den1);
    f2unpack(DAB, dab0, dab1); f2unpack(DAC, dac0, dac1);
    f2unpack(DBC, dbc0, dbc1);
    f2unpack(VI, vi0, vi1);    f2unpack(WI, wi0, wi1);

    float v0, w0, v1, w1;
    lane_sel(vb0, vc0, vbc0, den0, dab0, dac0, dbc0, ta0, tb0, tc0, vi0, wi0, v0, w0);
    lane_sel(vb1, vc1, vbc1, den1, dab1, dac1, dbc1, ta1, tb1, tc1, vi1, wi1, v1, w1);

    u64 NV = f2mul(f2pack(v0, v1), KN1);
    u64 NW = f2mul(f2pack(w0, w1), KN1);

    u64 DX = f2fma(NV, ABX, f2fma(NW, ACX, APX));
    u64 DY = f2fma(NV, ABY, f2fma(NW, ACY, APY));
    u64 DZ = f2fma(NV, ABZ, f2fma(NW, ACZ, APZ));
    u64 DIST = f2fma(DX, DX, f2fma(DY, DY, f2mul(DZ, DZ)));
    float dist0, dist1;
    f2unpack(DIST, dist0, dist1);

    top2_upd(dist0, te,     best, bidx, best2, bidx2);
    top2_upd(dist1, te + 1, best, bidx, best2, bidx2);
}

// ---------------------------------------------------------------------------
// Kernel 1: brute-force scan; 2 points per thread share each loaded triangle
// pair (amortized LDS + doubled ILP, R9-proven) with R11 sat-clamp body.
// Top-2 per (point, split); f64 arbitration downstream.
// ---------------------------------------------------------------------------
__global__ void __launch_bounds__(BLOCK, 4) k_main(const float* __restrict__ points) {
    __shared__ ulonglong2 sh[TILE_PAIRS * 10];
    int b = blockIdx.z;
    int q0 = blockIdx.x * (BLOCK * PTS_PER_THREAD) + threadIdx.x;
    int q1 = q0 + BLOCK;
    const float* pp0 = points + (size_t)(b * NQ + q0) * 3;
    const float* pp1 = points + (size_t)(b * NQ + q1) * 3;
    u64 PX0 = f2pack(pp0[0], pp0[0]), PY0 = f2pack(pp0[1], pp0[1]), PZ0 = f2pack(pp0[2], pp0[2]);
    u64 PX1 = f2pack(pp1[0], pp1[0]), PY1 = f2pack(pp1[1], pp1[1]), PZ1 = f2pack(pp1[2], pp1[2]);
    const u64 KN1 = f2pack(-1.0f, -1.0f);
    int pairBase = blockIdx.y * PAIRS_PER_SPLIT;

    float bestA  = 3.402823e38f;  int bidxA  = pairBase * 2;
    float bestA2 = 3.402823e38f;  int bidxA2 = pairBase * 2;
    float bestB  = 3.402823e38f;  int bidxB  = pairBase * 2;
    float bestB2 = 3.402823e38f;  int bidxB2 = pairBase * 2;

    for (int tp0 = 0; tp0 < PAIRS_PER_SPLIT; tp0 += TILE_PAIRS) {
        __syncthreads();
        {
            const float4* src = g_tc2 + (size_t)(b * (NF/2) + pairBase + tp0) * 10;
            float4* dst = (float4*)sh;
            for (int i = threadIdx.x; i < TILE_PAIRS * 10; i += BLOCK) dst[i] = src[i];
        }
        __syncthreads();

        #pragma unroll 2
        for (int j = 0; j < TILE_PAIRS; j++) {
            const ulonglong2* tp = sh + j * 10;
            ulonglong2 s0 = tp[0], s1 = tp[1], s2 = tp[2], s3 = tp[3], s4 = tp[4];
            ulonglong2 s5 = tp[5], s6 = tp[6], s7 = tp[7], s8 = tp[8], s9 = tp[9];
            u64 NAX = s0.x, NAY = s0.y, NAZ = s1.x, ABX = s1.y;
            u64 ABY = s2.x, ABZ = s2.y, ACX = s3.x, ACY = s3.y;
            u64 ACZ = s4.x, AA  = s4.y, BB  = s5.x, NGG = s5.y;
            u64 IA  = s6.x, IB  = s6.y, IC  = s7.x, ID  = s7.y;
            u64 AMG = s8.x, CB2 = s8.y, DEN = s9.x;

            int te = (pairBase + tp0 + j) * 2;
            eval_pair(PX0, PY0, PZ0, KN1,
                      NAX, NAY, NAZ, ABX, ABY, ABZ, ACX, ACY, ACZ, AA, BB, NGG,
                      IA, IB, IC, ID, AMG, CB2, DEN,
                      te, bestA, bidxA, bestA2, bidxA2);
            eval_pair(PX1, PY1, PZ1, KN1,
                      NAX, NAY, NAZ, ABX, ABY, ABZ, ACX, ACY, ACZ, AA, BB, NGG,
                      IA, IB, IC, ID, AMG, CB2, DEN,
                      te, bestB, bidxB, bestB2, bidxB2);
        }
    }

    g_cand[(size_t)(b * NQ + q0) * SPLITS + blockIdx.y] =
        make_uint2((unsigned)bidxA, (unsigned)bidxA2);
    g_cand[(size_t)(b * NQ + q1) * SPLITS + blockIdx.y] =
        make_uint2((unsigned)bidxB, (unsigned)bidxB2);
}

// ---------------------------------------------------------------------------
// Reference formula in DOUBLE precision (true-math ordering for arbitration).
// ---------------------------------------------------------------------------
__device__ void ref_eval_d(const float* __restrict__ tp,
                           double px, double py, double pz,
                           double& d2out, double& rxo, double& ryo, double& rzo) {
    double ax = tp[0], ay = tp[1], az = tp[2];
    double bx = tp[3], by = tp[4], bz = tp[5];
    double cx = tp[6], cy = tp[7], cz = tp[8];

    double abx = bx - ax, aby = by - ay, abz = bz - az;
    double acx = cx - ax, acy = cy - ay, acz = cz - az;
    double apx = px - ax, apy = py - ay, apz = pz - az;
    double d1 = abx*apx + aby*apy + abz*apz;
    double d2 = acx*apx + acy*apy + acz*apz;
    double bpx = px - bx, bpy = py - by, bpz = pz - bz;
    double d3 = abx*bpx + aby*bpy + abz*bpz;
    double d4 = acx*bpx + acy*bpy + acz*bpz;
    double cpx = px - cx, cpy = py - cy, cpz = pz - cz;
    double d5 = abx*cpx + aby*cpy + abz*cpz;
    double d6 = acx*cpx + acy*cpy + acz*cpz;

    double vc = d1*d4 - d3*d2;
    double vb = d5*d2 - d1*d6;
    double va = d3*d6 - d5*d4;
    double v_ab = dclamp01(dsafe_div(d1, d1 - d3));
    double w_ac = dclamp01(dsafe_div(d2, d2 - d6));
    double w_bc = dclamp01(dsafe_div(d4 - d3, (d4 - d3) + (d5 - d6)));
    double denom = va + vb + vc;
    double v = dsafe_div(vb, denom);
    double w = dsafe_div(vc, denom);

    double rx = ax + abx*v + acx*w;
    double ry = ay + aby*v + acy*w;
    double rz = az + abz*v + acz*w;

    bool m_bc = (va <= 0.0) && ((d4 - d3) >= 0.0) && ((d5 - d6) >= 0.0);
    if (m_bc) { rx = bx + w_bc*(cx - bx); ry = by + w_bc*(cy - by); rz = bz + w_bc*(cz - bz); }
    bool m_ac = (vb <= 0.0) && (d2 >= 0.0) && (d6 <= 0.0);
    if (m_ac) { rx = ax + w_ac*acx; ry = ay + w_ac*acy; rz = az + w_ac*acz; }
    bool m_ab = (vc <= 0.0) && (d1 >= 0.0) && (d3 <= 0.0);
    if (m_ab) { rx = ax + v_ab*abx; ry = ay + v_ab*aby; rz = az + v_ab*abz; }
    bool m_c = (d6 >= 0.0) && (d5 <= d6);
    if (m_c) { rx = cx; ry = cy; rz = cz; }
    bool m_b = (d3 >= 0.0) && (d4 <= d3);
    if (m_b) { rx = bx; ry = by; rz = bz; }
    bool m_a = (d1 <= 0.0) && (d2 <= 0.0);
    if (m_a) { rx = ax; ry = ay; rz = az; }

    double dxx = px - rx, dyy = py - ry, dzz = pz - rz;
    d2out = dxx*dxx + dyy*dyy + dzz*dzz;
    rxo = rx; ryo = ry; rzo = rz;
}

// ---------------------------------------------------------------------------
// Kernel 2: PARALLEL arbitration — 4 threads per point, each f64-evaluates 4
// of the 16 candidates; butterfly-reduce (bestD, bestI) with idx tie-break;
// sub-lane 0 recomputes the winner's closest point and writes outputs.
// ---------------------------------------------------------------------------
__global__ void k_fin(const float* __restrict__ tris,
                      const float* __restrict__ points,
                      float* __restrict__ out) {
    int gid = blockIdx.x * blockDim.x + threadIdx.x;
    int i = gid >> 2;         // point index
    int sub = gid & 3;        // quarter (splits 2*sub, 2*sub+1)
    if (i >= NPTS) return;
    int b = i / NQ;

    const float* pp = points + (size_t)i * 3;
    double px = pp[0], py = pp[1], pz = pp[2];

    double bestD = 1e300;
    int bestI = 0x7FFFFFFF;

    #pragma unroll
    for (int s = sub * 2; s < sub * 2 + 2; s++) {
        uint2 c = g_cand[(size_t)i * SPLITS + s];
        #pragma unroll
        for (int k = 0; k < 2; k++) {
            int idx = (k == 0) ? (int)c.x : (int)c.y;
            const float* tp = tris + (size_t)(b * NF + idx) * 9;
            double d2, rx, ry, rz;
            ref_eval_d(tp, px, py, pz, d2, rx, ry, rz);
            bool take = (d2 < bestD) || (d2 == bestD && idx < bestI);
            if (take) { bestD = d2; bestI = idx; }
        }
    }

    // butterfly reduce over the 4 sub-lanes (same warp: gid consecutive)
    #pragma unroll
    for (int off = 1; off < 4; off <<= 1) {
        double oD = __shfl_xor_sync(0xFFFFFFFFu, bestD, off);
        int    oI = __shfl_xor_sync(0xFFFFFFFFu, bestI, off);
        if (oD < bestD || (oD == bestD && oI < bestI)) { bestD = oD; bestI = oI; }
    }

    if (sub == 0) {
        const float* tp = tris + (size_t)(b * NF + bestI) * 9;
        double d2, rx, ry, rz;
        ref_eval_d(tp, px, py, pz, d2, rx, ry, rz);
        out[i] = (float)d2;                                  // distances [2,16384]
        out[NPTS + (size_t)i*3 + 0] = (float)rx;             // closest_points
        out[NPTS + (size_t)i*3 + 1] = (float)ry;
        out[NPTS + (size_t)i*3 + 2] = (float)rz;
        out[(size_t)NPTS*4 + i] = (float)bestI;              // closest_faces
    }
}

extern "C" void kernel_launch(void* const* d_in, const int* in_sizes, int n_in,
                              void* d_out, int out_size) {
    const float* tris = (const float*)d_in[0];   // [2,4096,3,3]
    const float* pts  = (const float*)d_in[1];   // [2,16384,3]
    float* out = (float*)d_out;

    k_pre<<<(NB*NF + 255) / 256, 256>>>(tris);
    dim3 grid(NQ / (BLOCK * PTS_PER_THREAD), SPLITS, NB);
    k_main<<<grid, BLOCK>>>(pts);
    k_fin<<<(NPTS * 4 + 255) / 256, 256>>>(tris, pts, out);
}